// round 1
// baseline (speedup 1.0000x reference)
#include <cuda_runtime.h>
#include <math.h>

#define CM 1024
#define TT 2048
#define BB 4
#define HH 16
#define MR (BB*TT)   // 8192 rows

// Scratch (device globals: allocation-free per harness rules)
__device__ float g_qkv[(size_t)MR * 3 * CM];   // [8192, 3072]
__device__ float g_att[(size_t)MR * CM];       // [8192, 1024]

// ---------------------------------------------------------------------------
// C[M,N] = A[M,K] * B[N,K]^T   (both row-major, K contiguous)
// 64x64 tile, BK=16, 128 threads, 4x8 per-thread micro-tile
// ---------------------------------------------------------------------------
__global__ __launch_bounds__(128) void gemm_tn_kernel(
    const float* __restrict__ A, const float* __restrict__ B,
    float* __restrict__ C, int M, int N, int K) {
  __shared__ float As[16][65];   // [kk][row], padded to cut transpose STS conflicts
  __shared__ float Bs[16][65];
  const int bm = blockIdx.y * 64;
  const int bn = blockIdx.x * 64;
  const int tid = threadIdx.x;
  const int ty = tid >> 3;       // 0..15 (row group)
  const int tx = tid & 7;        // 0..7  (col group)

  float acc[4][8];
#pragma unroll
  for (int i = 0; i < 4; i++)
#pragma unroll
    for (int j = 0; j < 8; j++) acc[i][j] = 0.f;

  for (int k0 = 0; k0 < K; k0 += 16) {
#pragma unroll
    for (int i = tid; i < 256; i += 128) {   // 256 float4 per 64x16 tile
      int row = i >> 2, kq = i & 3;
      float4 va = *(const float4*)(A + (size_t)(bm + row) * K + k0 + kq * 4);
      As[kq*4+0][row] = va.x; As[kq*4+1][row] = va.y;
      As[kq*4+2][row] = va.z; As[kq*4+3][row] = va.w;
      float4 vb = *(const float4*)(B + (size_t)(bn + row) * K + k0 + kq * 4);
      Bs[kq*4+0][row] = vb.x; Bs[kq*4+1][row] = vb.y;
      Bs[kq*4+2][row] = vb.z; Bs[kq*4+3][row] = vb.w;
    }
    __syncthreads();
#pragma unroll
    for (int kk = 0; kk < 16; kk++) {
      float a[4], b[8];
#pragma unroll
      for (int i = 0; i < 4; i++) a[i] = As[kk][ty*4 + i];
#pragma unroll
      for (int j = 0; j < 8; j++) b[j] = Bs[kk][tx*8 + j];
#pragma unroll
      for (int i = 0; i < 4; i++)
#pragma unroll
        for (int j = 0; j < 8; j++) acc[i][j] = fmaf(a[i], b[j], acc[i][j]);
    }
    __syncthreads();
  }

#pragma unroll
  for (int i = 0; i < 4; i++) {
    float* crow = C + (size_t)(bm + ty*4 + i) * N + bn + tx*8;
#pragma unroll
    for (int j = 0; j < 8; j++) crow[j] = acc[i][j];
  }
}

// ---------------------------------------------------------------------------
// Flash attention (causal), fp32. One CTA = 64 queries of one (b,h).
// qkv layout: [b*T + t][3*CM], q at col h*64, k at CM + h*64, v at 2*CM + h*64.
// SMEM: Qs[d][r] (stride 65), KPs[..] (K as [d][c] then P as [k][r], stride 65),
//       Vs[k][dim] (stride 64).
// ---------------------------------------------------------------------------
__global__ __launch_bounds__(128) void attn_kernel(const float* __restrict__ qkv,
                                                   float* __restrict__ att) {
  extern __shared__ float sm[];
  float* Qs  = sm;               // 64*65
  float* KPs = sm + 64*65;       // 64*65
  float* Vs  = sm + 2*64*65;     // 64*64
  const int qi = blockIdx.x, h = blockIdx.y, b = blockIdx.z;
  const int tid = threadIdx.x;
  const int ty = tid >> 3, tx = tid & 7;
  const int q0 = qi * 64;

  const float* qbase = qkv + (size_t)(b*TT + q0) * 3*CM + h*64;
  for (int i = tid; i < 1024; i += 128) {
    int r = i >> 4, dq = i & 15;
    float4 v = *(const float4*)(qbase + (size_t)r * 3*CM + dq*4);
    Qs[(dq*4+0)*65 + r] = v.x * 0.125f;   // fold 1/sqrt(64) into Q
    Qs[(dq*4+1)*65 + r] = v.y * 0.125f;
    Qs[(dq*4+2)*65 + r] = v.z * 0.125f;
    Qs[(dq*4+3)*65 + r] = v.w * 0.125f;
  }

  float m[4], l[4], o[4][8];
#pragma unroll
  for (int i = 0; i < 4; i++) {
    m[i] = -1e30f; l[i] = 0.f;
#pragma unroll
    for (int j = 0; j < 8; j++) o[i][j] = 0.f;
  }

  for (int kj = 0; kj <= qi; kj++) {
    const float* kbase = qkv + (size_t)(b*TT + kj*64) * 3*CM + CM + h*64;
    const float* vbase = kbase + CM;
    __syncthreads();   // previous iteration's P reads done before overwriting KPs
    for (int i = tid; i < 1024; i += 128) {
      int r = i >> 4, dq = i & 15;
      float4 kv = *(const float4*)(kbase + (size_t)r * 3*CM + dq*4);
      KPs[(dq*4+0)*65 + r] = kv.x;
      KPs[(dq*4+1)*65 + r] = kv.y;
      KPs[(dq*4+2)*65 + r] = kv.z;
      KPs[(dq*4+3)*65 + r] = kv.w;
      float4 vv = *(const float4*)(vbase + (size_t)r * 3*CM + dq*4);
      *(float4*)(Vs + r*64 + dq*4) = vv;
    }
    __syncthreads();

    // S = (Q*scale) K^T   -> s[4][8] per thread
    float s[4][8];
#pragma unroll
    for (int i = 0; i < 4; i++)
#pragma unroll
      for (int j = 0; j < 8; j++) s[i][j] = 0.f;
#pragma unroll 16
    for (int kk = 0; kk < 64; kk++) {
      float a[4], bb[8];
#pragma unroll
      for (int i = 0; i < 4; i++) a[i] = Qs[kk*65 + ty*4 + i];
#pragma unroll
      for (int j = 0; j < 8; j++) bb[j] = KPs[kk*65 + tx*8 + j];
#pragma unroll
      for (int i = 0; i < 4; i++)
#pragma unroll
        for (int j = 0; j < 8; j++) s[i][j] = fmaf(a[i], bb[j], s[i][j]);
    }

    if (kj == qi) {   // causal mask on the diagonal block
#pragma unroll
      for (int i = 0; i < 4; i++)
#pragma unroll
        for (int j = 0; j < 8; j++)
          if (tx*8 + j > ty*4 + i) s[i][j] = -1e30f;
    }

    // Online softmax, per row (8 tx-lanes share a row; lane bits 0-2 == tx)
#pragma unroll
    for (int i = 0; i < 4; i++) {
      float rm = s[i][0];
#pragma unroll
      for (int j = 1; j < 8; j++) rm = fmaxf(rm, s[i][j]);
      rm = fmaxf(rm, __shfl_xor_sync(0xffffffffu, rm, 1));
      rm = fmaxf(rm, __shfl_xor_sync(0xffffffffu, rm, 2));
      rm = fmaxf(rm, __shfl_xor_sync(0xffffffffu, rm, 4));
      float mn = fmaxf(m[i], rm);
      float alpha = __expf(m[i] - mn);
      float rs = 0.f;
#pragma unroll
      for (int j = 0; j < 8; j++) { s[i][j] = __expf(s[i][j] - mn); rs += s[i][j]; }
      rs += __shfl_xor_sync(0xffffffffu, rs, 1);
      rs += __shfl_xor_sync(0xffffffffu, rs, 2);
      rs += __shfl_xor_sync(0xffffffffu, rs, 4);
      l[i] = l[i] * alpha + rs;
      m[i] = mn;
#pragma unroll
      for (int j = 0; j < 8; j++) o[i][j] *= alpha;
    }

    // Stage P into KPs (K is consumed), then O += P @ V
    __syncthreads();
#pragma unroll
    for (int i = 0; i < 4; i++)
#pragma unroll
      for (int j = 0; j < 8; j++)
        KPs[(tx*8 + j)*65 + ty*4 + i] = s[i][j];
    __syncthreads();

#pragma unroll 16
    for (int kk = 0; kk < 64; kk++) {
      float p[4], vv[8];
#pragma unroll
      for (int i = 0; i < 4; i++) p[i] = KPs[kk*65 + ty*4 + i];
#pragma unroll
      for (int j = 0; j < 8; j++) vv[j] = Vs[kk*64 + tx*8 + j];
#pragma unroll
      for (int i = 0; i < 4; i++)
#pragma unroll
        for (int j = 0; j < 8; j++) o[i][j] = fmaf(p[i], vv[j], o[i][j]);
    }
  }

  // Epilogue: O /= l, write to [B,T,C] layout at head slot
#pragma unroll
  for (int i = 0; i < 4; i++) {
    float inv = 1.f / l[i];
    float* orow = att + (size_t)(b*TT + q0 + ty*4 + i) * CM + h*64 + tx*8;
#pragma unroll
    for (int j = 0; j < 8; j++) orow[j] = o[i][j] * inv;
  }
}

// ---------------------------------------------------------------------------
extern "C" void kernel_launch(void* const* d_in, const int* in_sizes, int n_in,
                              void* d_out, int out_size) {
  const float* x     = (const float*)d_in[0];   // [4,2048,1024]
  const float* w_qkv = (const float*)d_in[1];   // [3072,1024]
  const float* w_out = (const float*)d_in[2];   // [1024,1024]
  float* out = (float*)d_out;

  float *qkvp, *attp;
  cudaGetSymbolAddress((void**)&qkvp, g_qkv);
  cudaGetSymbolAddress((void**)&attp, g_att);

  // 1) QKV projection: [8192,3072] = x @ w_qkv^T
  gemm_tn_kernel<<<dim3(3*CM/64, MR/64), 128>>>(x, w_qkv, qkvp, MR, 3*CM, CM);

  // 2) Causal flash attention -> g_att [8192,1024]
  int smem = (2*64*65 + 64*64) * (int)sizeof(float);   // 49664 B
  cudaFuncSetAttribute(attn_kernel, cudaFuncAttributeMaxDynamicSharedMemorySize, smem);
  attn_kernel<<<dim3(TT/64, HH, BB), 128, smem>>>(qkvp, attp);

  // 3) Output projection: out = g_att @ w_out^T
  gemm_tn_kernel<<<dim3(CM/64, MR/64), 128>>>(attp, w_out, out, MR, CM, CM);
}

// round 4
// speedup vs baseline: 4.3087x; 4.3087x over previous
#include <cuda_runtime.h>
#include <cuda_bf16.h>
#include <cstdint>

#define CM 1024
#define TT 2048
#define BB 4
#define HH 16
#define MR (BB*TT)   // 8192 rows

// ---------------------------------------------------------------------------
// Scratch (device globals: allocation-free per harness rules)
// ---------------------------------------------------------------------------
__device__ __nv_bfloat16 g_x_hi[(size_t)MR * CM],     g_x_lo[(size_t)MR * CM];
__device__ __nv_bfloat16 g_wqkv_hi[3 * CM * CM],      g_wqkv_lo[3 * CM * CM];
__device__ __nv_bfloat16 g_wout_hi[CM * CM],          g_wout_lo[CM * CM];
__device__ __nv_bfloat16 g_qkv_hi[(size_t)MR * 3 * CM], g_qkv_lo[(size_t)MR * 3 * CM];
__device__ __nv_bfloat16 g_att_hi[(size_t)MR * CM],   g_att_lo[(size_t)MR * CM];

// ---------------------------------------------------------------------------
// helpers
// ---------------------------------------------------------------------------
__device__ __forceinline__ uint32_t smem_u32(const void* p) {
  uint32_t a;
  asm("{ .reg .u64 t; cvta.to.shared.u64 t, %1; cvt.u32.u64 %0, t; }"
      : "=r"(a) : "l"(p));
  return a;
}
__device__ __forceinline__ void cp16(uint32_t s, const void* g) {
  asm volatile("cp.async.cg.shared.global [%0], [%1], 16;" :: "r"(s), "l"(g));
}
#define CP_COMMIT() asm volatile("cp.async.commit_group;" ::: "memory")
#define CP_WAIT(n)  asm volatile("cp.async.wait_group %0;" :: "n"(n) : "memory")

// D += A*B, m16n8k16 bf16, fp32 accumulate
__device__ __forceinline__ void mma16(float* d, uint32_t a0, uint32_t a1,
                                      uint32_t a2, uint32_t a3,
                                      uint32_t b0, uint32_t b1) {
  asm volatile(
      "mma.sync.aligned.m16n8k16.row.col.f32.bf16.bf16.f32 "
      "{%0,%1,%2,%3}, {%4,%5,%6,%7}, {%8,%9}, {%0,%1,%2,%3};"
      : "+f"(d[0]), "+f"(d[1]), "+f"(d[2]), "+f"(d[3])
      : "r"(a0), "r"(a1), "r"(a2), "r"(a3), "r"(b0), "r"(b1));
}
__device__ __forceinline__ void ldsm4t(uint32_t& r0, uint32_t& r1,
                                       uint32_t& r2, uint32_t& r3, uint32_t a) {
  asm volatile("ldmatrix.sync.aligned.m8n8.x4.trans.shared.b16 "
               "{%0,%1,%2,%3}, [%4];"
               : "=r"(r0), "=r"(r1), "=r"(r2), "=r"(r3) : "r"(a));
}
__device__ __forceinline__ uint32_t ldu(const void* p) {
  return *(const uint32_t*)p;
}
__device__ __forceinline__ uint32_t sw128(uint32_t o) { return o ^ ((o >> 3) & 0x70); }

// split fp32 -> bf16 hi + bf16 lo (x = hi + lo + O(2^-18 x))
__device__ __forceinline__ void split1(float x, uint16_t& h, uint16_t& l) {
  __nv_bfloat16 bh = __float2bfloat16_rn(x);
  float r = x - __bfloat162float(bh);
  __nv_bfloat16 bl = __float2bfloat16_rn(r);
  h = __bfloat16_as_ushort(bh);
  l = __bfloat16_as_ushort(bl);
}

// ---------------------------------------------------------------------------
// elementwise split: fp32 -> (hi, lo) bf16
// ---------------------------------------------------------------------------
__global__ __launch_bounds__(256) void split_kernel(
    const float* __restrict__ in, __nv_bfloat16* __restrict__ hi,
    __nv_bfloat16* __restrict__ lo, int n4) {
  int i = blockIdx.x * blockDim.x + threadIdx.x;
  if (i >= n4) return;
  float4 v = ((const float4*)in)[i];
  uint16_t h0, h1, h2, h3, l0, l1, l2, l3;
  split1(v.x, h0, l0); split1(v.y, h1, l1);
  split1(v.z, h2, l2); split1(v.w, h3, l3);
  ((uint2*)hi)[i] = make_uint2(h0 | ((uint32_t)h1 << 16), h2 | ((uint32_t)h3 << 16));
  ((uint2*)lo)[i] = make_uint2(l0 | ((uint32_t)l1 << 16), l2 | ((uint32_t)l3 << 16));
}

// ---------------------------------------------------------------------------
// bf16x3 TN GEMM: C[M,N] = A[M,K] * B[N,K]^T, A/B given as bf16 hi/lo pairs.
// CTA 128x128, BK=64, 3-stage cp.async, 256 threads (8 warps: 2x4, 64x32 each)
// MODE 0: write fp32 C.  MODE 1: write bf16 hi/lo C.
// ---------------------------------------------------------------------------
#define GSMEM_TOTAL (3 * 65536)

template<int MODE>
__global__ __launch_bounds__(256) void gemm3(
    const __nv_bfloat16* __restrict__ Ah_, const __nv_bfloat16* __restrict__ Al_,
    const __nv_bfloat16* __restrict__ Bh_, const __nv_bfloat16* __restrict__ Bl_,
    float* __restrict__ Cf, __nv_bfloat16* __restrict__ Chi,
    __nv_bfloat16* __restrict__ Clo, int N, int K) {
  extern __shared__ char sm[];
  const int tid = threadIdx.x, w = tid >> 5, lane = tid & 31;
  const int g = lane >> 2, t = lane & 3;
  const int wm = w & 1, wn = w >> 1;
  const int bm = blockIdx.y * 128, bn = blockIdx.x * 128;

  float acc[4][4][4];
#pragma unroll
  for (int mt = 0; mt < 4; mt++)
#pragma unroll
    for (int nt = 0; nt < 4; nt++)
#pragma unroll
      for (int r = 0; r < 4; r++) acc[mt][nt][r] = 0.f;

  // stage: Ah | Al | Bh | Bl, each 128 rows x 128B (64 bf16), SW128 swizzled
  auto fill = [&](int s, int k0) {
    char* base = sm + s * 65536;
#pragma unroll
    for (int i = tid; i < 1024; i += 256) {
      int row = i >> 3, c = i & 7;
      uint32_t swo = sw128((uint32_t)(row * 128 + c * 16));
      size_t ao = (size_t)(bm + row) * K + k0 + c * 8;
      size_t bo = (size_t)(bn + row) * K + k0 + c * 8;
      cp16(smem_u32(base + swo),         Ah_ + ao);
      cp16(smem_u32(base + 16384 + swo), Al_ + ao);
      cp16(smem_u32(base + 32768 + swo), Bh_ + bo);
      cp16(smem_u32(base + 49152 + swo), Bl_ + bo);
    }
  };

  const int KT = K >> 6;
  fill(0, 0);   CP_COMMIT();
  fill(1, 64);  CP_COMMIT();
  fill(2, 128); CP_COMMIT();

  for (int c = 0; c < KT; c++) {
    const int s = c - (c / 3) * 3;
    CP_WAIT(2);
    __syncthreads();
    const char* Ah = sm + s * 65536;
    const char* Al = Ah + 16384;
    const char* Bh = Ah + 32768;
    const char* Bl = Ah + 49152;
#pragma unroll
    for (int kt = 0; kt < 4; kt++) {
      const uint32_t xo = ((uint32_t)(kt * 32 + t * 4)) ^ ((uint32_t)g << 4);
      uint32_t ah[4][4], al[4][4];
#pragma unroll
      for (int mt = 0; mt < 4; mt++) {
        const char* ar  = Ah + (wm * 64 + mt * 16 + g) * 128;
        const char* arl = Al + (wm * 64 + mt * 16 + g) * 128;
        ah[mt][0] = ldu(ar + xo);          ah[mt][1] = ldu(ar + 1024 + xo);
        ah[mt][2] = ldu(ar + (xo ^ 16));   ah[mt][3] = ldu(ar + 1024 + (xo ^ 16));
        al[mt][0] = ldu(arl + xo);         al[mt][1] = ldu(arl + 1024 + xo);
        al[mt][2] = ldu(arl + (xo ^ 16));  al[mt][3] = ldu(arl + 1024 + (xo ^ 16));
      }
#pragma unroll
      for (int nt = 0; nt < 4; nt++) {
        const char* br  = Bh + (wn * 32 + nt * 8 + g) * 128;
        const char* brl = Bl + (wn * 32 + nt * 8 + g) * 128;
        uint32_t bh0 = ldu(br + xo),  bh1 = ldu(br + (xo ^ 16));
        uint32_t bl0 = ldu(brl + xo), bl1 = ldu(brl + (xo ^ 16));
#pragma unroll
        for (int mt = 0; mt < 4; mt++) {
          mma16(acc[mt][nt], ah[mt][0], ah[mt][1], ah[mt][2], ah[mt][3], bh0, bh1);
          mma16(acc[mt][nt], ah[mt][0], ah[mt][1], ah[mt][2], ah[mt][3], bl0, bl1);
          mma16(acc[mt][nt], al[mt][0], al[mt][1], al[mt][2], al[mt][3], bh0, bh1);
        }
      }
    }
    __syncthreads();
    if (c + 3 < KT) fill(s, (c + 3) * 64);
    CP_COMMIT();
  }

#pragma unroll
  for (int mt = 0; mt < 4; mt++) {
#pragma unroll
    for (int nt = 0; nt < 4; nt++) {
      const int row = bm + wm * 64 + mt * 16 + g;
      const int col = bn + wn * 32 + nt * 8 + 2 * t;
      if (MODE == 0) {
        *(float2*)(Cf + (size_t)row * N + col) =
            make_float2(acc[mt][nt][0], acc[mt][nt][1]);
        *(float2*)(Cf + (size_t)(row + 8) * N + col) =
            make_float2(acc[mt][nt][2], acc[mt][nt][3]);
      } else {
        uint16_t h0, l0, h1, l1;
        split1(acc[mt][nt][0], h0, l0); split1(acc[mt][nt][1], h1, l1);
        *(uint32_t*)(Chi + (size_t)row * N + col) = h0 | ((uint32_t)h1 << 16);
        *(uint32_t*)(Clo + (size_t)row * N + col) = l0 | ((uint32_t)l1 << 16);
        split1(acc[mt][nt][2], h0, l0); split1(acc[mt][nt][3], h1, l1);
        *(uint32_t*)(Chi + (size_t)(row + 8) * N + col) = h0 | ((uint32_t)h1 << 16);
        *(uint32_t*)(Clo + (size_t)(row + 8) * N + col) = l0 | ((uint32_t)l1 << 16);
      }
    }
  }
}

// ---------------------------------------------------------------------------
// bf16x3 causal flash attention. CTA = 64 queries of one (b,h), 4 warps.
// SMEM: Qh 8K | Ql 8K | Kh x2 16K | Kl x2 16K | Vh x2 16K | Vl x2 16K = 80KB
// P stays in registers (accumulator layout == A-fragment layout for k16).
// V transposed on load via ldmatrix.x4.trans.
// ---------------------------------------------------------------------------
#define AQH 0
#define AQL 8192
#define AKH 16384
#define AKL 32768
#define AVH 49152
#define AVL 65536
#define ASMEM_TOTAL 81920

__global__ __launch_bounds__(128) void attn3(
    const __nv_bfloat16* __restrict__ qh, const __nv_bfloat16* __restrict__ ql,
    __nv_bfloat16* __restrict__ oh, __nv_bfloat16* __restrict__ ol) {
  extern __shared__ char sm[];
  const int qi = blockIdx.x, h = blockIdx.y, b = blockIdx.z;
  const int tid = threadIdx.x, w = tid >> 5, lane = tid & 31;
  const int g = lane >> 2, t = lane & 3;
  const int q0 = qi * 64;
  const int r0 = w * 16 + g;
  const size_t rowQ = (size_t)(b * TT + q0);

  auto fillKV = [&](int kb, int bf) {
    const size_t base = (size_t)(b * TT + kb * 64) * 3 * CM + CM + h * 64;
    char* kh = sm + AKH + bf * 8192;
    char* kl = sm + AKL + bf * 8192;
    char* vh = sm + AVH + bf * 8192;
    char* vl = sm + AVL + bf * 8192;
#pragma unroll
    for (int i = tid; i < 512; i += 128) {
      int row = i >> 3, c = i & 7;
      uint32_t swo = sw128((uint32_t)(row * 128 + c * 16));
      size_t src = base + (size_t)row * 3 * CM + c * 8;
      cp16(smem_u32(kh + swo), qh + src);
      cp16(smem_u32(kl + swo), ql + src);
      cp16(smem_u32(vh + swo), qh + src + CM);
      cp16(smem_u32(vl + swo), ql + src + CM);
    }
  };

  // prologue: Q + KV block 0, one group
#pragma unroll
  for (int i = tid; i < 512; i += 128) {
    int row = i >> 3, c = i & 7;
    uint32_t swo = sw128((uint32_t)(row * 128 + c * 16));
    size_t src = (rowQ + row) * 3 * CM + h * 64 + c * 8;
    cp16(smem_u32(sm + AQH + swo), qh + src);
    cp16(smem_u32(sm + AQL + swo), ql + src);
  }
  fillKV(0, 0);
  CP_COMMIT();

  float m0 = -1e30f, m1 = -1e30f, l0 = 0.f, l1 = 0.f;
  float o[8][4];
#pragma unroll
  for (int j = 0; j < 8; j++)
#pragma unroll
    for (int r = 0; r < 4; r++) o[j][r] = 0.f;

  for (int kj = 0; kj <= qi; kj++) {
    const int buf = kj & 1;
    if (kj < qi) fillKV(kj + 1, buf ^ 1);
    CP_COMMIT();
    CP_WAIT(1);
    __syncthreads();

    const char* Kh = sm + AKH + buf * 8192;
    const char* Kl = sm + AKL + buf * 8192;
    const char* Qh = sm + AQH;
    const char* Ql = sm + AQL;
    const uint32_t vhU = smem_u32(sm + AVH + buf * 8192);
    const uint32_t vlU = smem_u32(sm + AVL + buf * 8192);

    // ---- S = Q K^T (3-pass bf16) ----
    float s[8][4];
#pragma unroll
    for (int j = 0; j < 8; j++)
#pragma unroll
      for (int r = 0; r < 4; r++) s[j][r] = 0.f;

#pragma unroll
    for (int kt = 0; kt < 4; kt++) {
      const uint32_t xo = ((uint32_t)(kt * 32 + t * 4)) ^ ((uint32_t)g << 4);
      const char* qrh = Qh + r0 * 128;
      const char* qrl = Ql + r0 * 128;
      uint32_t ah0 = ldu(qrh + xo),        ah1 = ldu(qrh + 1024 + xo);
      uint32_t ah2 = ldu(qrh + (xo ^ 16)), ah3 = ldu(qrh + 1024 + (xo ^ 16));
      uint32_t al0 = ldu(qrl + xo),        al1 = ldu(qrl + 1024 + xo);
      uint32_t al2 = ldu(qrl + (xo ^ 16)), al3 = ldu(qrl + 1024 + (xo ^ 16));
#pragma unroll
      for (int j = 0; j < 8; j++) {
        const char* krh = Kh + (j * 8 + g) * 128;
        const char* krl = Kl + (j * 8 + g) * 128;
        uint32_t bh0 = ldu(krh + xo), bh1 = ldu(krh + (xo ^ 16));
        uint32_t bl0 = ldu(krl + xo), bl1 = ldu(krl + (xo ^ 16));
        mma16(s[j], ah0, ah1, ah2, ah3, bh0, bh1);
        mma16(s[j], ah0, ah1, ah2, ah3, bl0, bl1);
        mma16(s[j], al0, al1, al2, al3, bh0, bh1);
      }
    }

    // scale 1/sqrt(64), causal mask on diagonal block
#pragma unroll
    for (int j = 0; j < 8; j++)
#pragma unroll
      for (int r = 0; r < 4; r++) s[j][r] *= 0.125f;

    if (kj == qi) {
#pragma unroll
      for (int j = 0; j < 8; j++) {
        const int c = j * 8 + 2 * t;
        if (c     > r0)     s[j][0] = -1e30f;
        if (c + 1 > r0)     s[j][1] = -1e30f;
        if (c     > r0 + 8) s[j][2] = -1e30f;
        if (c + 1 > r0 + 8) s[j][3] = -1e30f;
      }
    }

    // ---- online softmax (rows r0, r0+8; 4 quad lanes share a row) ----
    float rm0 = -1e30f, rm1 = -1e30f;
#pragma unroll
    for (int j = 0; j < 8; j++) {
      rm0 = fmaxf(rm0, fmaxf(s[j][0], s[j][1]));
      rm1 = fmaxf(rm1, fmaxf(s[j][2], s[j][3]));
    }
    rm0 = fmaxf(rm0, __shfl_xor_sync(0xffffffffu, rm0, 1));
    rm0 = fmaxf(rm0, __shfl_xor_sync(0xffffffffu, rm0, 2));
    rm1 = fmaxf(rm1, __shfl_xor_sync(0xffffffffu, rm1, 1));
    rm1 = fmaxf(rm1, __shfl_xor_sync(0xffffffffu, rm1, 2));
    const float mn0 = fmaxf(m0, rm0), mn1 = fmaxf(m1, rm1);
    const float al_0 = __expf(m0 - mn0), al_1 = __expf(m1 - mn1);
    float rs0 = 0.f, rs1 = 0.f;
#pragma unroll
    for (int j = 0; j < 8; j++) {
      s[j][0] = __expf(s[j][0] - mn0);
      s[j][1] = __expf(s[j][1] - mn0);
      s[j][2] = __expf(s[j][2] - mn1);
      s[j][3] = __expf(s[j][3] - mn1);
      rs0 += s[j][0] + s[j][1];
      rs1 += s[j][2] + s[j][3];
    }
    rs0 += __shfl_xor_sync(0xffffffffu, rs0, 1);
    rs0 += __shfl_xor_sync(0xffffffffu, rs0, 2);
    rs1 += __shfl_xor_sync(0xffffffffu, rs1, 1);
    rs1 += __shfl_xor_sync(0xffffffffu, rs1, 2);
    l0 = l0 * al_0 + rs0;  m0 = mn0;
    l1 = l1 * al_1 + rs1;  m1 = mn1;
#pragma unroll
    for (int j = 0; j < 8; j++) {
      o[j][0] *= al_0; o[j][1] *= al_0;
      o[j][2] *= al_1; o[j][3] *= al_1;
    }

    // ---- split P in registers (accumulator layout == A-frag layout) ----
    uint32_t ph01[8], ph23[8], pl01[8], pl23[8];
#pragma unroll
    for (int j = 0; j < 8; j++) {
      uint16_t h0, l0_, h1, l1_;
      split1(s[j][0], h0, l0_); split1(s[j][1], h1, l1_);
      ph01[j] = h0 | ((uint32_t)h1 << 16);
      pl01[j] = l0_ | ((uint32_t)l1_ << 16);
      split1(s[j][2], h0, l0_); split1(s[j][3], h1, l1_);
      ph23[j] = h0 | ((uint32_t)h1 << 16);
      pl23[j] = l0_ | ((uint32_t)l1_ << 16);
    }

    // ---- O += P V (3-pass; V^T fragments via ldmatrix.x4.trans) ----
    const int qq = lane >> 3, rr = lane & 7;
#pragma unroll
    for (int kt = 0; kt < 4; kt++) {
      const uint32_t pa0 = ph01[2*kt],   pa1 = ph23[2*kt];
      const uint32_t pa2 = ph01[2*kt+1], pa3 = ph23[2*kt+1];
      const uint32_t qa0 = pl01[2*kt],   qa1 = pl23[2*kt];
      const uint32_t qa2 = pl01[2*kt+1], qa3 = pl23[2*kt+1];
      const uint32_t vrow = (uint32_t)(kt * 16 + ((qq & 1) << 3) + rr);
#pragma unroll
      for (int jp = 0; jp < 4; jp++) {
        const uint32_t off = sw128(vrow * 128 + (uint32_t)(jp * 32 + ((qq >> 1) << 4)));
        uint32_t vh0, vh1, vh2, vh3, vl0, vl1, vl2, vl3;
        ldsm4t(vh0, vh1, vh2, vh3, vhU + off);
        ldsm4t(vl0, vl1, vl2, vl3, vlU + off);
        mma16(o[2*jp],     pa0, pa1, pa2, pa3, vh0, vh1);
        mma16(o[2*jp],     pa0, pa1, pa2, pa3, vl0, vl1);
        mma16(o[2*jp],     qa0, qa1, qa2, qa3, vh0, vh1);
        mma16(o[2*jp + 1], pa0, pa1, pa2, pa3, vh2, vh3);
        mma16(o[2*jp + 1], pa0, pa1, pa2, pa3, vl2, vl3);
        mma16(o[2*jp + 1], qa0, qa1, qa2, qa3, vh2, vh3);
      }
    }
    __syncthreads();   // tiles consumed before next prefetch overwrites
  }

  // ---- epilogue: O /= l, split to hi/lo bf16 ----
  const float i0 = 1.f / l0, i1 = 1.f / l1;
  const size_t ro0 = (rowQ + r0) * CM + h * 64;
  const size_t ro1 = ro0 + 8 * (size_t)CM;
#pragma unroll
  for (int j = 0; j < 8; j++) {
    const int col = j * 8 + 2 * t;
    uint16_t h0, l0_, h1, l1_;
    split1(o[j][0] * i0, h0, l0_); split1(o[j][1] * i0, h1, l1_);
    *(uint32_t*)(oh + ro0 + col) = h0 | ((uint32_t)h1 << 16);
    *(uint32_t*)(ol + ro0 + col) = l0_ | ((uint32_t)l1_ << 16);
    split1(o[j][2] * i1, h0, l0_); split1(o[j][3] * i1, h1, l1_);
    *(uint32_t*)(oh + ro1 + col) = h0 | ((uint32_t)h1 << 16);
    *(uint32_t*)(ol + ro1 + col) = l0_ | ((uint32_t)l1_ << 16);
  }
}

// ---------------------------------------------------------------------------
extern "C" void kernel_launch(void* const* d_in, const int* in_sizes, int n_in,
                              void* d_out, int out_size) {
  const float* x     = (const float*)d_in[0];   // [4,2048,1024]
  const float* w_qkv = (const float*)d_in[1];   // [3072,1024]
  const float* w_out = (const float*)d_in[2];   // [1024,1024]
  float* out = (float*)d_out;

  __nv_bfloat16 *xh, *xl, *wqh, *wql, *woh, *wol, *qkvh, *qkvl, *ath, *atl;
  cudaGetSymbolAddress((void**)&xh,  g_x_hi);    cudaGetSymbolAddress((void**)&xl,  g_x_lo);
  cudaGetSymbolAddress((void**)&wqh, g_wqkv_hi); cudaGetSymbolAddress((void**)&wql, g_wqkv_lo);
  cudaGetSymbolAddress((void**)&woh, g_wout_hi); cudaGetSymbolAddress((void**)&wol, g_wout_lo);
  cudaGetSymbolAddress((void**)&qkvh, g_qkv_hi); cudaGetSymbolAddress((void**)&qkvl, g_qkv_lo);
  cudaGetSymbolAddress((void**)&ath, g_att_hi);  cudaGetSymbolAddress((void**)&atl, g_att_lo);

  cudaFuncSetAttribute(gemm3<0>, cudaFuncAttributeMaxDynamicSharedMemorySize, GSMEM_TOTAL);
  cudaFuncSetAttribute(gemm3<1>, cudaFuncAttributeMaxDynamicSharedMemorySize, GSMEM_TOTAL);
  cudaFuncSetAttribute(attn3,    cudaFuncAttributeMaxDynamicSharedMemorySize, ASMEM_TOTAL);

  // 0) split inputs into bf16 hi/lo
  {
    int n4 = MR * CM / 4;
    split_kernel<<<(n4 + 255) / 256, 256>>>(x, xh, xl, n4);
    n4 = 3 * CM * CM / 4;
    split_kernel<<<(n4 + 255) / 256, 256>>>(w_qkv, wqh, wql, n4);
    n4 = CM * CM / 4;
    split_kernel<<<(n4 + 255) / 256, 256>>>(w_out, woh, wol, n4);
  }

  // 1) QKV projection -> qkv hi/lo bf16
  gemm3<1><<<dim3(3*CM/128, MR/128), 256, GSMEM_TOTAL>>>(
      xh, xl, wqh, wql, nullptr, qkvh, qkvl, 3*CM, CM);

  // 2) causal flash attention -> att hi/lo bf16
  attn3<<<dim3(TT/64, HH, BB), 128, ASMEM_TOTAL>>>(qkvh, qkvl, ath, atl);

  // 3) output projection -> fp32 out
  gemm3<0><<<dim3(CM/128, MR/128), 256, GSMEM_TOTAL>>>(
      ath, atl, woh, wol, out, nullptr, nullptr, CM, CM);
}